// round 4
// baseline (speedup 1.0000x reference)
#include <cuda_runtime.h>
#include <math.h>

#define BATCH 64
#define TSEQ  256
#define DIN   256
#define HDIM  512
#define G4H   2048
#define NCTA  128     // recurrence CTAs; each owns 4 hidden units (16 gate rows)
#define UPC   4       // units per CTA
#define RPC   16      // gate rows per CTA

// ---------------- scratch (device globals; no allocation allowed) ----------
__device__ float g_G[(size_t)BATCH * TSEQ * G4H];       // Wih@x + b_ih + b_hh
__device__ unsigned long long g_hpair[2][HDIM];         // (tag<<32)|h  double buffer
__device__ float g_hall[BATCH * HDIM];                  // h at end of each sample
__device__ float g_z1[BATCH * 1024];
__device__ float g_z2[BATCH * 1024];

// ---------------- fast activations (err ~1e-6, budget 1e-3) ----------------
__device__ __forceinline__ float sig_f(float x) {
    return __fdividef(1.f, 1.f + __expf(-x));
}
__device__ __forceinline__ float tanh_f(float x) {
    return 1.f - 2.f * __fdividef(1.f, __expf(2.f * x) + 1.f);
}

// ---------------- init: reset state every graph replay ---------------------
__global__ void init_kernel() {
    int tid = threadIdx.x;
    if (tid < HDIM) {
        // tag -1 in both buffers; buffer 1 (parity of step -1) holds h0 = 0
        unsigned long long p = ((unsigned long long)(unsigned)(-1) << 32);
        g_hpair[0][tid] = p;
        g_hpair[1][tid] = p;   // value bits 0 => h = 0.0f
    }
}

// ---------------- X projection GEMM: G = X @ Wih^T + (b_ih + b_hh) ---------
#define BM 64
#define BN 64
#define BK 32
__global__ void __launch_bounds__(256) xproj_kernel(
    const float* __restrict__ X, const float* __restrict__ Wih,
    const float* __restrict__ bih, const float* __restrict__ bhh,
    const int* __restrict__ starts, const int* __restrict__ ends)
{
    const int bn = blockIdx.x;
    const int bm = blockIdx.y;
    const int R0 = bm * BM;
    const int b  = R0 >> 8;
    const int t0 = R0 & 255;

    // skip tiles with no active timesteps: active iff t in (start, end]
    const int st = starts[b], en = ends[b];
    if (max(t0, st + 1) > min(t0 + BM - 1, en)) return;

    __shared__ float As[BK][BM];
    __shared__ float Bs[BK][BN];

    const int tid = threadIdx.x;
    const int tx = tid & 15, ty = tid >> 4;
    float acc[4][4] = {};

    for (int k0 = 0; k0 < DIN; k0 += BK) {
        #pragma unroll
        for (int i = 0; i < 2; i++) {
            int idx = tid + i * 256;
            int row = idx >> 3, k4 = idx & 7;
            float4 v = *(const float4*)(X + (size_t)(R0 + row) * DIN + k0 + k4 * 4);
            As[k4*4+0][row] = v.x; As[k4*4+1][row] = v.y;
            As[k4*4+2][row] = v.z; As[k4*4+3][row] = v.w;
            float4 u = *(const float4*)(Wih + (size_t)(bn * BN + row) * DIN + k0 + k4 * 4);
            Bs[k4*4+0][row] = u.x; Bs[k4*4+1][row] = u.y;
            Bs[k4*4+2][row] = u.z; Bs[k4*4+3][row] = u.w;
        }
        __syncthreads();
        #pragma unroll
        for (int kk = 0; kk < BK; kk++) {
            float a[4], bb[4];
            #pragma unroll
            for (int p = 0; p < 4; p++) a[p]  = As[kk][ty * 4 + p];
            #pragma unroll
            for (int q = 0; q < 4; q++) bb[q] = Bs[kk][tx * 4 + q];
            #pragma unroll
            for (int p = 0; p < 4; p++)
                #pragma unroll
                for (int q = 0; q < 4; q++)
                    acc[p][q] += a[p] * bb[q];
        }
        __syncthreads();
    }

    #pragma unroll
    for (int q = 0; q < 4; q++) {
        int col = bn * BN + tx * 4 + q;
        float bias = bih[col] + bhh[col];
        #pragma unroll
        for (int p = 0; p < 4; p++) {
            int row = R0 + ty * 4 + p;
            g_G[(size_t)row * G4H + col] = acc[p][q] + bias;
        }
    }
}

// ---------------- sequential LSTM recurrence (persistent, 128 CTAs) --------
// CTA s owns units [4s, 4s+4) = 16 gate rows; warp w handles local gate-row w
// (gate = w>>2, unit = w&3). W row is register-resident (16 floats/thread).
// Exchange: tagged 8B words in L2, double-buffered by step parity.
__global__ void __launch_bounds__(512, 1) recur_kernel(
    const float* __restrict__ Whh,
    const int* __restrict__ starts, const int* __restrict__ ends)
{
    const int s = blockIdx.x;
    const int tid = threadIdx.x;
    const int w = tid >> 5, l = tid & 31;

    __shared__ float h_sm[HDIM];
    __shared__ float act_sm[RPC];
    __shared__ int st_sm[BATCH], en_sm[BATCH];

    if (tid < BATCH) { st_sm[tid] = starts[tid]; en_sm[tid] = ends[tid]; }

    // this warp's gate-row of W_hh, register resident
    const int gate = w >> 2, ul = w & 3;
    const int grow = gate * HDIM + s * UPC + ul;   // row in [0, 2048)
    float Wreg[16];
    {
        const float* wr = Whh + (size_t)grow * HDIM;
        #pragma unroll
        for (int j = 0; j < 16; j++) Wreg[j] = wr[l + 32 * j];
    }
    __syncthreads();   // st_sm/en_sm visible

    float creg = 0.f;                       // cell state for unit s*4+tid (tid<4)
    int b = 0, t = st_sm[0] + 1, en = en_sm[0];
    int step = 0;

    // prefetch first step's G value (lane 0 of each warp)
    float Gc = 0.f;
    if (l == 0) Gc = __ldg(&g_G[(size_t)(b * TSEQ + t) * G4H + grow]);

    while (b < BATCH) {
        // next step coords + G prefetch (one step ahead; hides DRAM latency)
        int nb = b, nt = t + 1, nen = en;
        if (nt > en) {
            nb = b + 1;
            nt  = (nb < BATCH) ? st_sm[nb] + 1 : 0;
            nen = (nb < BATCH) ? en_sm[nb] : 0;
        }
        float Gn = 0.f;
        if (l == 0 && nb < BATCH)
            Gn = __ldg(&g_G[(size_t)(nb * TSEQ + nt) * G4H + grow]);

        // poll my h element of step-1 (tag check == data valid)
        {
            const unsigned long long* src = &g_hpair[(step + 1) & 1][tid];
            const int expect = step - 1;
            unsigned long long v;
            do {
                asm volatile("ld.relaxed.gpu.global.b64 %0, [%1];"
                             : "=l"(v) : "l"(src) : "memory");
            } while ((int)(v >> 32) != expect);
            h_sm[tid] = __uint_as_float((unsigned)v);
        }
        __syncthreads();

        // matvec: one full gate-row per warp (16 elems/lane, 4 acc chains)
        float a0 = 0.f, a1 = 0.f, a2 = 0.f, a3 = 0.f;
        #pragma unroll
        for (int j = 0; j < 4; j++) {
            a0 += Wreg[4*j+0] * h_sm[l + 32 * (4*j+0)];
            a1 += Wreg[4*j+1] * h_sm[l + 32 * (4*j+1)];
            a2 += Wreg[4*j+2] * h_sm[l + 32 * (4*j+2)];
            a3 += Wreg[4*j+3] * h_sm[l + 32 * (4*j+3)];
        }
        float a = (a0 + a1) + (a2 + a3);
        #pragma unroll
        for (int off = 16; off >= 1; off >>= 1)
            a += __shfl_xor_sync(0xffffffffu, a, off);

        // distributed activation: lane 0 of each warp handles its row
        if (l == 0) {
            float gv = Gc + a;
            act_sm[w] = (gate == 2) ? tanh_f(gv) : sig_f(gv);
        }
        __syncthreads();

        // owner update + publish (4 threads)
        if (tid < UPC) {
            float I  = act_sm[tid];
            float F  = act_sm[4 + tid];
            float Gt = act_sm[8 + tid];
            float O  = act_sm[12 + tid];
            float c  = F * creg + I * Gt;
            creg = c;
            float hn = O * tanh_f(c);
            unsigned long long pv =
                ((unsigned long long)(unsigned)step << 32) | __float_as_uint(hn);
            asm volatile("st.relaxed.gpu.global.b64 [%0], %1;"
                         :: "l"(&g_hpair[step & 1][s * UPC + tid]), "l"(pv)
                         : "memory");
            if (t == en) g_hall[b * HDIM + s * UPC + tid] = hn;
        }

        Gc = Gn; b = nb; t = nt; en = nen; step++;
    }
}

// ---------------- MLP head: C[64,N] = relu(A[64,K] @ W[N,K]^T + b) ---------
template<int LAYER>
__global__ void __launch_bounds__(256) mlp_gemm_kernel(
    const float* __restrict__ W, const float* __restrict__ bias)
{
    const int K = (LAYER == 0) ? HDIM : 1024;
    const float* A = (LAYER == 0) ? g_hall : g_z1;
    float* C = (LAYER == 0) ? g_z1 : g_z2;
    const int N = 1024;

    const int bn = blockIdx.x;
    __shared__ float As[BK][BM];
    __shared__ float Bs[BK][BN];

    const int tid = threadIdx.x;
    const int tx = tid & 15, ty = tid >> 4;
    float acc[4][4] = {};

    for (int k0 = 0; k0 < K; k0 += BK) {
        #pragma unroll
        for (int i = 0; i < 2; i++) {
            int idx = tid + i * 256;
            int row = idx >> 3, k4 = idx & 7;
            float4 v = *(const float4*)(A + (size_t)row * K + k0 + k4 * 4);
            As[k4*4+0][row] = v.x; As[k4*4+1][row] = v.y;
            As[k4*4+2][row] = v.z; As[k4*4+3][row] = v.w;
            float4 u = *(const float4*)(W + (size_t)(bn * BN + row) * K + k0 + k4 * 4);
            Bs[k4*4+0][row] = u.x; Bs[k4*4+1][row] = u.y;
            Bs[k4*4+2][row] = u.z; Bs[k4*4+3][row] = u.w;
        }
        __syncthreads();
        #pragma unroll
        for (int kk = 0; kk < BK; kk++) {
            float a[4], bb[4];
            #pragma unroll
            for (int p = 0; p < 4; p++) a[p]  = As[kk][ty * 4 + p];
            #pragma unroll
            for (int q = 0; q < 4; q++) bb[q] = Bs[kk][tx * 4 + q];
            #pragma unroll
            for (int p = 0; p < 4; p++)
                #pragma unroll
                for (int q = 0; q < 4; q++)
                    acc[p][q] += a[p] * bb[q];
        }
        __syncthreads();
    }

    #pragma unroll
    for (int q = 0; q < 4; q++) {
        int col = bn * BN + tx * 4 + q;
        float bv = bias[col];
        #pragma unroll
        for (int p = 0; p < 4; p++) {
            int row = ty * 4 + p;
            C[(size_t)row * N + col] = fmaxf(acc[p][q] + bv, 0.f);
        }
    }
}

__global__ void __launch_bounds__(256) mlp3_kernel(
    const float* __restrict__ W3, const float* __restrict__ b3,
    const float* __restrict__ tv, float* __restrict__ out, int out_size)
{
    const int b = blockIdx.x, tid = threadIdx.x;
    const float* z = g_z2 + (size_t)b * 1024;
    float acc = 0.f;
    for (int k = tid; k < 1024; k += 256) acc += W3[k] * z[k];
    #pragma unroll
    for (int off = 16; off >= 1; off >>= 1) acc += __shfl_xor_sync(0xffffffffu, acc, off);
    __shared__ float ws[8];
    if ((tid & 31) == 0) ws[tid >> 5] = acc;
    __syncthreads();
    if (tid == 0) {
        float ssum = 0.f;
        #pragma unroll
        for (int i = 0; i < 8; i++) ssum += ws[i];
        out[b] = 1.f / (1.f + expf(-(ssum + b3[0])));
        if (64 + b < out_size) out[64 + b] = tv[b];   // pass-through true_vals
    }
}

// ---------------- launch --------------------------------------------------
extern "C" void kernel_launch(void* const* d_in, const int* in_sizes, int n_in,
                              void* d_out, int out_size)
{
    const float* x      = (const float*)d_in[0];
    const float* tv     = (const float*)d_in[1];
    const float* W_ih   = (const float*)d_in[2];
    const float* W_hh   = (const float*)d_in[3];
    const float* b_ih   = (const float*)d_in[4];
    const float* b_hh   = (const float*)d_in[5];
    const float* W1     = (const float*)d_in[6];
    const float* b1     = (const float*)d_in[7];
    const float* W2     = (const float*)d_in[8];
    const float* b2     = (const float*)d_in[9];
    const float* W3     = (const float*)d_in[10];
    const float* b3     = (const float*)d_in[11];
    const int*   starts = (const int*)d_in[12];
    const int*   ends   = (const int*)d_in[13];
    float* out = (float*)d_out;

    init_kernel<<<1, 512>>>();

    dim3 ggrid(G4H / BN, (BATCH * TSEQ) / BM);
    xproj_kernel<<<ggrid, 256>>>(x, W_ih, b_ih, b_hh, starts, ends);

    recur_kernel<<<NCTA, 512>>>(W_hh, starts, ends);

    mlp_gemm_kernel<0><<<16, 256>>>(W1, b1);
    mlp_gemm_kernel<1><<<16, 256>>>(W2, b2);
    mlp3_kernel<<<BATCH, 256>>>(W3, b3, tv, out, out_size);
}

// round 6
// speedup vs baseline: 1.0945x; 1.0945x over previous
#include <cuda_runtime.h>
#include <math.h>

#define BATCH 64
#define TSEQ  256
#define DIN   256
#define HDIM  512
#define G4H   2048
#define NCTA  64      // recurrence CTAs; each owns 8 hidden units (32 gate rows)
#define UPC   8       // units per CTA
#define RPC   32      // gate rows per CTA
#define NMIR  4       // mirrored h-exchange buffers

// ---------------- scratch (device globals; no allocation allowed) ----------
__device__ float g_G[(size_t)BATCH * TSEQ * G4H];        // Wih@x + b_ih + b_hh
__device__ unsigned long long g_hmir[NMIR][2][HDIM];     // (tag<<32)|h, 4 replicas x 2 parities
__device__ float g_hall[BATCH * HDIM];                   // h at end of each sample
__device__ float g_z1[BATCH * 1024];
__device__ float g_z2[BATCH * 1024];

// ---------------- fast activations (err ~1e-6, budget 1e-3) ----------------
__device__ __forceinline__ float sig_f(float x) {
    return __fdividef(1.f, 1.f + __expf(-x));
}
__device__ __forceinline__ float tanh_f(float x) {
    return 1.f - 2.f * __fdividef(1.f, __expf(2.f * x) + 1.f);
}

// ---------------- init: reset state every graph replay ---------------------
__global__ void init_kernel() {
    int tid = threadIdx.x;
    // tag -1 everywhere; value bits 0 => h0 = 0.0f (read by step-0 poll)
    unsigned long long p = ((unsigned long long)(unsigned)(-1) << 32);
    #pragma unroll
    for (int m = 0; m < NMIR; m++) {
        g_hmir[m][0][tid] = p;
        g_hmir[m][1][tid] = p;
    }
}

// ---------------- X projection GEMM: G = X @ Wih^T + (b_ih + b_hh) ---------
#define BM 64
#define BN 64
#define BK 32
__global__ void __launch_bounds__(256) xproj_kernel(
    const float* __restrict__ X, const float* __restrict__ Wih,
    const float* __restrict__ bih, const float* __restrict__ bhh,
    const int* __restrict__ starts, const int* __restrict__ ends)
{
    const int bn = blockIdx.x;
    const int bm = blockIdx.y;
    const int R0 = bm * BM;
    const int b  = R0 >> 8;
    const int t0 = R0 & 255;

    // skip tiles with no active timesteps: active iff t in (start, end]
    const int st = starts[b], en = ends[b];
    if (max(t0, st + 1) > min(t0 + BM - 1, en)) return;

    __shared__ float As[BK][BM];
    __shared__ float Bs[BK][BN];

    const int tid = threadIdx.x;
    const int tx = tid & 15, ty = tid >> 4;
    float acc[4][4] = {};

    for (int k0 = 0; k0 < DIN; k0 += BK) {
        #pragma unroll
        for (int i = 0; i < 2; i++) {
            int idx = tid + i * 256;
            int row = idx >> 3, k4 = idx & 7;
            float4 v = *(const float4*)(X + (size_t)(R0 + row) * DIN + k0 + k4 * 4);
            As[k4*4+0][row] = v.x; As[k4*4+1][row] = v.y;
            As[k4*4+2][row] = v.z; As[k4*4+3][row] = v.w;
            float4 u = *(const float4*)(Wih + (size_t)(bn * BN + row) * DIN + k0 + k4 * 4);
            Bs[k4*4+0][row] = u.x; Bs[k4*4+1][row] = u.y;
            Bs[k4*4+2][row] = u.z; Bs[k4*4+3][row] = u.w;
        }
        __syncthreads();
        #pragma unroll
        for (int kk = 0; kk < BK; kk++) {
            float a[4], bb[4];
            #pragma unroll
            for (int p = 0; p < 4; p++) a[p]  = As[kk][ty * 4 + p];
            #pragma unroll
            for (int q = 0; q < 4; q++) bb[q] = Bs[kk][tx * 4 + q];
            #pragma unroll
            for (int p = 0; p < 4; p++)
                #pragma unroll
                for (int q = 0; q < 4; q++)
                    acc[p][q] += a[p] * bb[q];
        }
        __syncthreads();
    }

    #pragma unroll
    for (int q = 0; q < 4; q++) {
        int col = bn * BN + tx * 4 + q;
        float bias = bih[col] + bhh[col];
        #pragma unroll
        for (int p = 0; p < 4; p++) {
            int row = R0 + ty * 4 + p;
            g_G[(size_t)row * G4H + col] = acc[p][q] + bias;
        }
    }
}

// ---------------- sequential LSTM recurrence (persistent, 64 CTAs) ---------
// CTA s owns units [8s, 8s+8) = 32 gate rows. Warp w handles local rows 2w
// and 2w+1 (row lr: gate = lr>>3, unit = lr&7). Per-lane W slice is register
// resident over 4 contiguous columns x 4 passes (float4 LDS on h).
// Exchange: tagged 8B words in L2, 4 replicas; consumer polls replica s&3.
__global__ void __launch_bounds__(512, 1) recur_kernel(
    const float* __restrict__ Whh,
    const int* __restrict__ starts, const int* __restrict__ ends)
{
    const int s = blockIdx.x;
    const int tid = threadIdx.x;
    const int w = tid >> 5, l = tid & 31;

    __shared__ float h_sm[HDIM];
    __shared__ float act_sm[RPC];
    __shared__ int st_sm[BATCH], en_sm[BATCH];

    if (tid < BATCH) { st_sm[tid] = starts[tid]; en_sm[tid] = ends[tid]; }

    // two gate rows for this warp
    const int lr0 = 2 * w, lr1 = 2 * w + 1;
    const int grow0 = (lr0 >> 3) * HDIM + s * UPC + (lr0 & 7);
    const int grow1 = (lr1 >> 3) * HDIM + s * UPC + (lr1 & 7);

    // register-resident W rows: lane l covers cols {128p + 4l .. 4l+3}
    float W0[4][4], W1[4][4];
    {
        const float* wr0 = Whh + (size_t)grow0 * HDIM;
        const float* wr1 = Whh + (size_t)grow1 * HDIM;
        #pragma unroll
        for (int p = 0; p < 4; p++) {
            float4 v0 = *(const float4*)(wr0 + 128 * p + 4 * l);
            W0[p][0] = v0.x; W0[p][1] = v0.y; W0[p][2] = v0.z; W0[p][3] = v0.w;
            float4 v1 = *(const float4*)(wr1 + 128 * p + 4 * l);
            W1[p][0] = v1.x; W1[p][1] = v1.y; W1[p][2] = v1.z; W1[p][3] = v1.w;
        }
    }
    __syncthreads();   // st_sm/en_sm visible

    // which G row does this lane prefetch? lane 0 -> row lr0, lane 16 -> lr1
    const int mygrow = (l == 16) ? grow1 : grow0;
    const int mylr   = (l == 16) ? lr1 : lr0;
    const int mygate = mylr >> 3;

    float creg = 0.f;                      // cell state for unit s*8+tid (tid<8)
    int b = 0, t = st_sm[0] + 1, en = en_sm[0];
    int step = 0;

    float Gc = 0.f;
    if (l == 0 || l == 16)
        Gc = __ldg(&g_G[(size_t)(b * TSEQ + t) * G4H + mygrow]);

    const int mir = s & (NMIR - 1);        // my polling replica

    while (b < BATCH) {
        // next step coords + G prefetch (one step ahead; hides DRAM latency)
        int nb = b, nt = t + 1, nen = en;
        if (nt > en) {
            nb = b + 1;
            nt  = (nb < BATCH) ? st_sm[nb] + 1 : 0;
            nen = (nb < BATCH) ? en_sm[nb] : 0;
        }
        float Gn = 0.f;
        if ((l == 0 || l == 16) && nb < BATCH)
            Gn = __ldg(&g_G[(size_t)(nb * TSEQ + nt) * G4H + mygrow]);

        // poll my h element of step-1 in my replica (tag check == data valid)
        {
            const unsigned long long* src = &g_hmir[mir][(step + 1) & 1][tid];
            const int expect = step - 1;
            unsigned long long v;
            do {
                asm volatile("ld.relaxed.gpu.global.b64 %0, [%1];"
                             : "=l"(v) : "l"(src) : "memory");
            } while ((int)(v >> 32) != expect);
            h_sm[tid] = __uint_as_float((unsigned)v);
        }
        __syncthreads();

        // matvec: 2 rows/warp; lane covers 4 contiguous cols x 4 passes
        float a0 = 0.f, a1 = 0.f;
        #pragma unroll
        for (int p = 0; p < 4; p++) {
            float4 hv = *(const float4*)(h_sm + 128 * p + 4 * l);
            a0 += W0[p][0] * hv.x + W0[p][1] * hv.y
                + W0[p][2] * hv.z + W0[p][3] * hv.w;
            a1 += W1[p][0] * hv.x + W1[p][1] * hv.y
                + W1[p][2] * hv.z + W1[p][3] * hv.w;
        }
        #pragma unroll
        for (int off = 16; off >= 1; off >>= 1) {
            a0 += __shfl_xor_sync(0xffffffffu, a0, off);
            a1 += __shfl_xor_sync(0xffffffffu, a1, off);
        }

        // distributed activation: lane 0 -> row 2w, lane 16 -> row 2w+1
        if (l == 0 || l == 16) {
            float gv = Gc + ((l == 16) ? a1 : a0);
            act_sm[mylr] = (mygate == 2) ? tanh_f(gv) : sig_f(gv);
        }
        __syncthreads();

        // owner update + publish to all replicas (8 threads)
        if (tid < UPC) {
            float I  = act_sm[tid];
            float F  = act_sm[UPC + tid];
            float Gt = act_sm[2 * UPC + tid];
            float O  = act_sm[3 * UPC + tid];
            float c  = F * creg + I * Gt;
            creg = c;
            float hn = O * tanh_f(c);
            unsigned long long pv =
                ((unsigned long long)(unsigned)step << 32) | __float_as_uint(hn);
            const int widx = s * UPC + tid;
            #pragma unroll
            for (int m = 0; m < NMIR; m++) {
                asm volatile("st.relaxed.gpu.global.b64 [%0], %1;"
                             :: "l"(&g_hmir[m][step & 1][widx]), "l"(pv)
                             : "memory");
            }
            if (t == en) g_hall[b * HDIM + widx] = hn;
        }

        Gc = Gn; b = nb; t = nt; en = nen; step++;
    }
}

// ---------------- MLP head: C[64,N] = relu(A[64,K] @ W[N,K]^T + b) ---------
template<int LAYER>
__global__ void __launch_bounds__(256) mlp_gemm_kernel(
    const float* __restrict__ W, const float* __restrict__ bias)
{
    const int K = (LAYER == 0) ? HDIM : 1024;
    const float* A = (LAYER == 0) ? g_hall : g_z1;
    float* C = (LAYER == 0) ? g_z1 : g_z2;
    const int N = 1024;

    const int bn = blockIdx.x;
    __shared__ float As[BK][BM];
    __shared__ float Bs[BK][BN];

    const int tid = threadIdx.x;
    const int tx = tid & 15, ty = tid >> 4;
    float acc[4][4] = {};

    for (int k0 = 0; k0 < K; k0 += BK) {
        #pragma unroll
        for (int i = 0; i < 2; i++) {
            int idx = tid + i * 256;
            int row = idx >> 3, k4 = idx & 7;
            float4 v = *(const float4*)(A + (size_t)row * K + k0 + k4 * 4);
            As[k4*4+0][row] = v.x; As[k4*4+1][row] = v.y;
            As[k4*4+2][row] = v.z; As[k4*4+3][row] = v.w;
            float4 u = *(const float4*)(W + (size_t)(bn * BN + row) * K + k0 + k4 * 4);
            Bs[k4*4+0][row] = u.x; Bs[k4*4+1][row] = u.y;
            Bs[k4*4+2][row] = u.z; Bs[k4*4+3][row] = u.w;
        }
        __syncthreads();
        #pragma unroll
        for (int kk = 0; kk < BK; kk++) {
            float a[4], bb[4];
            #pragma unroll
            for (int p = 0; p < 4; p++) a[p]  = As[kk][ty * 4 + p];
            #pragma unroll
            for (int q = 0; q < 4; q++) bb[q] = Bs[kk][tx * 4 + q];
            #pragma unroll
            for (int p = 0; p < 4; p++)
                #pragma unroll
                for (int q = 0; q < 4; q++)
                    acc[p][q] += a[p] * bb[q];
        }
        __syncthreads();
    }

    #pragma unroll
    for (int q = 0; q < 4; q++) {
        int col = bn * BN + tx * 4 + q;
        float bv = bias[col];
        #pragma unroll
        for (int p = 0; p < 4; p++) {
            int row = ty * 4 + p;
            C[(size_t)row * N + col] = fmaxf(acc[p][q] + bv, 0.f);
        }
    }
}

__global__ void __launch_bounds__(256) mlp3_kernel(
    const float* __restrict__ W3, const float* __restrict__ b3,
    const float* __restrict__ tv, float* __restrict__ out, int out_size)
{
    const int b = blockIdx.x, tid = threadIdx.x;
    const float* z = g_z2 + (size_t)b * 1024;
    float acc = 0.f;
    for (int k = tid; k < 1024; k += 256) acc += W3[k] * z[k];
    #pragma unroll
    for (int off = 16; off >= 1; off >>= 1) acc += __shfl_xor_sync(0xffffffffu, acc, off);
    __shared__ float ws[8];
    if ((tid & 31) == 0) ws[tid >> 5] = acc;
    __syncthreads();
    if (tid == 0) {
        float ssum = 0.f;
        #pragma unroll
        for (int i = 0; i < 8; i++) ssum += ws[i];
        out[b] = 1.f / (1.f + expf(-(ssum + b3[0])));
        if (64 + b < out_size) out[64 + b] = tv[b];   // pass-through true_vals
    }
}

// ---------------- launch --------------------------------------------------
extern "C" void kernel_launch(void* const* d_in, const int* in_sizes, int n_in,
                              void* d_out, int out_size)
{
    const float* x      = (const float*)d_in[0];
    const float* tv     = (const float*)d_in[1];
    const float* W_ih   = (const float*)d_in[2];
    const float* W_hh   = (const float*)d_in[3];
    const float* b_ih   = (const float*)d_in[4];
    const float* b_hh   = (const float*)d_in[5];
    const float* W1     = (const float*)d_in[6];
    const float* b1     = (const float*)d_in[7];
    const float* W2     = (const float*)d_in[8];
    const float* b2     = (const float*)d_in[9];
    const float* W3     = (const float*)d_in[10];
    const float* b3     = (const float*)d_in[11];
    const int*   starts = (const int*)d_in[12];
    const int*   ends   = (const int*)d_in[13];
    float* out = (float*)d_out;

    init_kernel<<<1, 512>>>();

    dim3 ggrid(G4H / BN, (BATCH * TSEQ) / BM);
    xproj_kernel<<<ggrid, 256>>>(x, W_ih, b_ih, b_hh, starts, ends);

    recur_kernel<<<NCTA, 512>>>(W_hh, starts, ends);

    mlp_gemm_kernel<0><<<16, 256>>>(W1, b1);
    mlp_gemm_kernel<1><<<16, 256>>>(W2, b2);
    mlp3_kernel<<<BATCH, 256>>>(W3, b3, tv, out, out_size);
}